// round 2
// baseline (speedup 1.0000x reference)
#include <cuda_runtime.h>
#include <cstdint>

// Problem constants
#define BB   128   // batch
#define INW  256   // input width
#define HH   1024  // hidden
#define NP   512   // pairs per A layer
#define LP   128   // number of (A,B) layer pairs (L=256 layers total)

// Static device scratch (no allocation allowed)
__device__ float4 g_trigA[LP][NP];          // {cos t0, sin t0, cos t1, sin t1}
__device__ float4 g_trigB[LP][NP];          // only [0..510] valid per layer
__device__ float  g_pR[4][BB * HH];         // GEMM partials per K-chunk
__device__ float  g_pI[4][BB * HH];

// ---------------------------------------------------------------------------
// Kernel 1: blocks [0,128) = complex GEMM (K-split x4, N-tiles of 32)
//           blocks [128,256) = trig table build (one block per layer pair)
// ---------------------------------------------------------------------------
__global__ __launch_bounds__(256) void k1(
    const float* __restrict__ inR, const float* __restrict__ inI,
    const float* __restrict__ wR,  const float* __restrict__ wI,
    const float* __restrict__ A0,  const float* __restrict__ A1,
    const float* __restrict__ B0,  const float* __restrict__ B1)
{
    const int bid = blockIdx.x, tid = threadIdx.x;

    if (bid >= 128) {
        // ---- trig table for layer pair k ----
        const int k = bid - 128;
        for (int idx = tid; idx < NP; idx += 256) {
            float c0, s0, c1, s1;
            sincosf(A0[k * NP + idx], &s0, &c0);
            sincosf(A1[k * NP + idx], &s1, &c1);
            g_trigA[k][idx] = make_float4(c0, s0, c1, s1);
        }
        for (int idx = tid; idx < NP - 1; idx += 256) {
            float c0, s0, c1, s1;
            sincosf(B0[k * (NP - 1) + idx], &s0, &c0);
            sincosf(B1[k * (NP - 1) + idx], &s1, &c1);
            g_trigB[k][idx] = make_float4(c0, s0, c1, s1);
        }
        return;
    }

    // ---- complex GEMM: tile M=128, N=32, K-chunk=64 ----
    const int kc = bid >> 5, nt = bid & 31;
    const int k0 = kc * 64, n0 = nt * 32;

    __shared__ float sXR[32][132], sXI[32][132];  // [k][m], padded rows (16B aligned)
    __shared__ float sWR[32][33],  sWI[32][33];   // [k][n], padded

    float accR[8][2], accI[8][2];
    #pragma unroll
    for (int r = 0; r < 8; r++)
        #pragma unroll
        for (int c = 0; c < 2; c++) { accR[r][c] = 0.f; accI[r][c] = 0.f; }

    const int mi = tid >> 4, ni = tid & 15;         // compute mapping: 8 rows x 2 cols
    const int lm = tid & 127, kh = (tid >> 7) * 16; // X load mapping
    const int wn = tid >> 3,  wk = (tid & 7) * 4;   // W load mapping

    for (int ks = 0; ks < 64; ks += 32) {
        __syncthreads();
        // load X tile (transpose to [k][m])
        #pragma unroll
        for (int j = 0; j < 4; j++) {
            const int kk = kh + j * 4;
            float4 vR = *(const float4*)(inR + lm * INW + k0 + ks + kk);
            float4 vI = *(const float4*)(inI + lm * INW + k0 + ks + kk);
            sXR[kk+0][lm] = vR.x; sXR[kk+1][lm] = vR.y;
            sXR[kk+2][lm] = vR.z; sXR[kk+3][lm] = vR.w;
            sXI[kk+0][lm] = vI.x; sXI[kk+1][lm] = vI.y;
            sXI[kk+2][lm] = vI.z; sXI[kk+3][lm] = vI.w;
        }
        // load W tile (transpose to [k][n])
        {
            float4 vR = *(const float4*)(wR + (n0 + wn) * INW + k0 + ks + wk);
            float4 vI = *(const float4*)(wI + (n0 + wn) * INW + k0 + ks + wk);
            sWR[wk+0][wn] = vR.x; sWR[wk+1][wn] = vR.y;
            sWR[wk+2][wn] = vR.z; sWR[wk+3][wn] = vR.w;
            sWI[wk+0][wn] = vI.x; sWI[wk+1][wn] = vI.y;
            sWI[wk+2][wn] = vI.z; sWI[wk+3][wn] = vI.w;
        }
        __syncthreads();

        #pragma unroll 8
        for (int kk = 0; kk < 32; kk++) {
            float aRv[8], aIv[8], bRv[2], bIv[2];
            *(float4*)&aRv[0] = *(const float4*)&sXR[kk][mi * 8];
            *(float4*)&aRv[4] = *(const float4*)&sXR[kk][mi * 8 + 4];
            *(float4*)&aIv[0] = *(const float4*)&sXI[kk][mi * 8];
            *(float4*)&aIv[4] = *(const float4*)&sXI[kk][mi * 8 + 4];
            bRv[0] = sWR[kk][ni*2]; bRv[1] = sWR[kk][ni*2+1];
            bIv[0] = sWI[kk][ni*2]; bIv[1] = sWI[kk][ni*2+1];
            #pragma unroll
            for (int r = 0; r < 8; r++)
                #pragma unroll
                for (int c = 0; c < 2; c++) {
                    accR[r][c] += aRv[r]*bRv[c] - aIv[r]*bIv[c];
                    accI[r][c] += aRv[r]*bIv[c] + aIv[r]*bRv[c];
                }
        }
    }

    #pragma unroll
    for (int r = 0; r < 8; r++) {
        const int m = mi * 8 + r;
        #pragma unroll
        for (int c = 0; c < 2; c++) {
            g_pR[kc][m * HH + n0 + ni*2 + c] = accR[r][c];
            g_pI[kc][m * HH + n0 + ni*2 + c] = accI[r][c];
        }
    }
}

// ---------------------------------------------------------------------------
// cp.async helpers (16B, register-free prefetch into smem)
// ---------------------------------------------------------------------------
__device__ __forceinline__ void cp_async16(void* smem_dst, const void* gmem_src) {
    uint32_t s = (uint32_t)__cvta_generic_to_shared(smem_dst);
    asm volatile("cp.async.cg.shared.global [%0], [%1], 16;\n"
                 :: "r"(s), "l"(gmem_src) : "memory");
}
__device__ __forceinline__ void cp_async_commit() {
    asm volatile("cp.async.commit_group;\n" ::: "memory");
}
__device__ __forceinline__ void cp_async_wait1() {
    asm volatile("cp.async.wait_group 1;\n" ::: "memory");
}

// ---------------------------------------------------------------------------
// Kernel 2: Clements mesh (register-resident state, 1 CTA per batch row)
//           trig double-buffered into smem via cp.async (latency decoupled)
//           + omega rotation + ih add + modReLU epilogue
// ---------------------------------------------------------------------------
__global__ __launch_bounds__(512, 1) void k2(
    const float* __restrict__ stR, const float* __restrict__ stI,
    const float* __restrict__ bR,  const float* __restrict__ bI,
    const float* __restrict__ om,  const float* __restrict__ mb,
    float* __restrict__ out)
{
    const int b = blockIdx.x, t = threadIdx.x;
    __shared__ float4 sA[2][512];
    __shared__ float4 sB[2][512];
    __shared__ float2 ex[512];

    // thread t owns channels (2t, 2t+1)
    float2 vr = ((const float2*)(stR + b * HH))[t];
    float2 vi = ((const float2*)(stI + b * HH))[t];
    float ar = vr.x, br = vr.y, ai = vi.x, bi = vi.y;

    // Preload layer-pair 0 trig (each thread copies exactly what it will read)
    cp_async16(&sA[0][t], &g_trigA[0][t]);
    cp_async16(&sB[0][t], &g_trigB[0][t]);
    cp_async_commit();

    for (int k = 0; k < LP; k++) {
        // Issue prefetch of next layer pair into the other buffer (no dest regs)
        if (k + 1 < LP) {
            cp_async16(&sA[(k + 1) & 1][t], &g_trigA[k + 1][t]);
            cp_async16(&sB[(k + 1) & 1][t], &g_trigB[k + 1][t]);
        }
        cp_async_commit();
        cp_async_wait1();   // current buffer's (self-copied) data is ready

        float4 ta = sA[k & 1][t];
        float4 tb = sB[k & 1][t];

        // ---- layer A: pair (2t, 2t+1), fully thread-local ----
        {
            float pr  = ta.x*ar - ta.y*ai;
            float pii = ta.y*ar + ta.x*ai;
            float nar = ta.z*pr  - ta.w*bi;
            float nai = ta.z*pii + ta.w*br;
            float nbr = ta.z*br  - ta.w*pii;
            float nbi = ta.z*bi  + ta.w*pr;
            ar = nar; ai = nai; br = nbr; bi = nbi;
        }

        // ---- layer B: pair (2t+1, 2t+2) -> neighbor exchange through smem ----
        ex[t] = make_float2(ar, ai);
        __syncthreads();
        if (t < 511) {
            float2 na = ex[t + 1];             // neighbor's channel 2t+2
            float pr  = tb.x*br - tb.y*bi;     // a-arm = my channel 2t+1
            float pii = tb.y*br + tb.x*bi;
            float obr = tb.z*na.x - tb.w*pii;  // new channel 2t+2 (back to neighbor)
            float obi = tb.z*na.y + tb.w*pr;
            float nbr = tb.z*pr  - tb.w*na.y;  // new channel 2t+1 (mine)
            float nbi = tb.z*pii + tb.w*na.x;
            ex[t + 1] = make_float2(obr, obi);
            br = nbr; bi = nbi;
        }
        __syncthreads();
        if (t > 0) { float2 v = ex[t]; ar = v.x; ai = v.y; }
    }

    // ---- epilogue ----
    const int ch = 2 * t;
    float ihR0 = bR[ch],     ihI0 = bI[ch];
    float ihR1 = bR[ch + 1], ihI1 = bI[ch + 1];
    #pragma unroll
    for (int c = 0; c < 4; c++) {
        float2 pr2 = ((const float2*)&g_pR[c][b * HH])[t];
        float2 pi2 = ((const float2*)&g_pI[c][b * HH])[t];
        ihR0 += pr2.x; ihR1 += pr2.y;
        ihI0 += pi2.x; ihI1 += pi2.y;
    }

    float co0, so0, co1, so1;
    sincosf(om[ch],     &so0, &co0);
    sincosf(om[ch + 1], &so1, &co1);

    float zr0 = ihR0 + co0*ar - so0*ai;
    float zi0 = ihI0 + so0*ar + co0*ai;
    float zr1 = ihR1 + co1*br - so1*bi;
    float zi1 = ihI1 + so1*br + co1*bi;

    float mag0 = sqrtf(zr0*zr0 + zi0*zi0);
    float mag1 = sqrtf(zr1*zr1 + zi1*zi1);
    float sc0 = fmaxf(mag0 + mb[ch],     0.f) / fmaxf(mag0, 1e-8f);
    float sc1 = fmaxf(mag1 + mb[ch + 1], 0.f) / fmaxf(mag1, 1e-8f);

    ((float2*)(out + b * HH))[t]           = make_float2(sc0*zr0, sc1*zr1);
    ((float2*)(out + BB * HH + b * HH))[t] = make_float2(sc0*zi0, sc1*zi1);
}

// ---------------------------------------------------------------------------
extern "C" void kernel_launch(void* const* d_in, const int* in_sizes, int n_in,
                              void* d_out, int out_size)
{
    const float* inR = (const float*)d_in[0];
    const float* inI = (const float*)d_in[1];
    const float* stR = (const float*)d_in[2];
    const float* stI = (const float*)d_in[3];
    const float* wR  = (const float*)d_in[4];
    const float* wI  = (const float*)d_in[5];
    const float* bR  = (const float*)d_in[6];
    const float* bI  = (const float*)d_in[7];
    const float* A0  = (const float*)d_in[8];
    const float* A1  = (const float*)d_in[9];
    const float* B0  = (const float*)d_in[10];
    const float* B1  = (const float*)d_in[11];
    const float* om  = (const float*)d_in[12];
    const float* mb  = (const float*)d_in[13];
    float* out = (float*)d_out;

    k1<<<256, 256>>>(inR, inI, wR, wI, A0, A1, B0, B1);
    k2<<<128, 512>>>(stR, stI, bR, bI, om, mb, out);
}

// round 3
// speedup vs baseline: 1.7300x; 1.7300x over previous
#include <cuda_runtime.h>
#include <cstdint>

// Problem constants
#define BB   128   // batch
#define INW  256   // input width
#define HH   1024  // hidden
#define NP   512   // pairs per A layer
#define LP   128   // number of (A,B) layer pairs (L=256 layers total)

// Static device scratch (no allocation allowed)
__device__ float4 g_trigA[LP][NP];          // {cos t0, sin t0, cos t1, sin t1}
__device__ float4 g_trigB[LP][NP];          // idx 511 = identity MZI
__device__ float  g_pR[4][BB * HH];         // GEMM partials per K-chunk
__device__ float  g_pI[4][BB * HH];

// ---------------------------------------------------------------------------
// Kernel 1: blocks [0,128) = complex GEMM (K-split x4, N-tiles of 32)
//           blocks [128,256) = trig table build (one block per layer pair)
// ---------------------------------------------------------------------------
__global__ __launch_bounds__(256) void k1(
    const float* __restrict__ inR, const float* __restrict__ inI,
    const float* __restrict__ wR,  const float* __restrict__ wI,
    const float* __restrict__ A0,  const float* __restrict__ A1,
    const float* __restrict__ B0,  const float* __restrict__ B1)
{
    const int bid = blockIdx.x, tid = threadIdx.x;

    if (bid >= 128) {
        // ---- trig table for layer pair k ----
        const int k = bid - 128;
        for (int idx = tid; idx < NP; idx += 256) {
            float c0, s0, c1, s1;
            sincosf(A0[k * NP + idx], &s0, &c0);
            sincosf(A1[k * NP + idx], &s1, &c1);
            g_trigA[k][idx] = make_float4(c0, s0, c1, s1);
        }
        for (int idx = tid; idx < NP; idx += 256) {
            // idx 511: identity MZI (angles 0) so thread 511's math stays finite
            float ang0 = (idx < NP - 1) ? B0[k * (NP - 1) + idx] : 0.f;
            float ang1 = (idx < NP - 1) ? B1[k * (NP - 1) + idx] : 0.f;
            float c0, s0, c1, s1;
            sincosf(ang0, &s0, &c0);
            sincosf(ang1, &s1, &c1);
            g_trigB[k][idx] = make_float4(c0, s0, c1, s1);
        }
        return;
    }

    // ---- complex GEMM: tile M=128, N=32, K-chunk=64 ----
    const int kc = bid >> 5, nt = bid & 31;
    const int k0 = kc * 64, n0 = nt * 32;

    __shared__ float sXR[32][132], sXI[32][132];  // [k][m], padded rows
    __shared__ float sWR[32][33],  sWI[32][33];   // [k][n], padded

    float accR[8][2], accI[8][2];
    #pragma unroll
    for (int r = 0; r < 8; r++)
        #pragma unroll
        for (int c = 0; c < 2; c++) { accR[r][c] = 0.f; accI[r][c] = 0.f; }

    const int mi = tid >> 4, ni = tid & 15;
    const int lm = tid & 127, kh = (tid >> 7) * 16;
    const int wn = tid >> 3,  wk = (tid & 7) * 4;

    for (int ks = 0; ks < 64; ks += 32) {
        __syncthreads();
        #pragma unroll
        for (int j = 0; j < 4; j++) {
            const int kk = kh + j * 4;
            float4 vR = *(const float4*)(inR + lm * INW + k0 + ks + kk);
            float4 vI = *(const float4*)(inI + lm * INW + k0 + ks + kk);
            sXR[kk+0][lm] = vR.x; sXR[kk+1][lm] = vR.y;
            sXR[kk+2][lm] = vR.z; sXR[kk+3][lm] = vR.w;
            sXI[kk+0][lm] = vI.x; sXI[kk+1][lm] = vI.y;
            sXI[kk+2][lm] = vI.z; sXI[kk+3][lm] = vI.w;
        }
        {
            float4 vR = *(const float4*)(wR + (n0 + wn) * INW + k0 + ks + wk);
            float4 vI = *(const float4*)(wI + (n0 + wn) * INW + k0 + ks + wk);
            sWR[wk+0][wn] = vR.x; sWR[wk+1][wn] = vR.y;
            sWR[wk+2][wn] = vR.z; sWR[wk+3][wn] = vR.w;
            sWI[wk+0][wn] = vI.x; sWI[wk+1][wn] = vI.y;
            sWI[wk+2][wn] = vI.z; sWI[wk+3][wn] = vI.w;
        }
        __syncthreads();

        #pragma unroll 8
        for (int kk = 0; kk < 32; kk++) {
            float aRv[8], aIv[8], bRv[2], bIv[2];
            *(float4*)&aRv[0] = *(const float4*)&sXR[kk][mi * 8];
            *(float4*)&aRv[4] = *(const float4*)&sXR[kk][mi * 8 + 4];
            *(float4*)&aIv[0] = *(const float4*)&sXI[kk][mi * 8];
            *(float4*)&aIv[4] = *(const float4*)&sXI[kk][mi * 8 + 4];
            bRv[0] = sWR[kk][ni*2]; bRv[1] = sWR[kk][ni*2+1];
            bIv[0] = sWI[kk][ni*2]; bIv[1] = sWI[kk][ni*2+1];
            #pragma unroll
            for (int r = 0; r < 8; r++)
                #pragma unroll
                for (int c = 0; c < 2; c++) {
                    accR[r][c] += aRv[r]*bRv[c] - aIv[r]*bIv[c];
                    accI[r][c] += aRv[r]*bIv[c] + aIv[r]*bRv[c];
                }
        }
    }

    #pragma unroll
    for (int r = 0; r < 8; r++) {
        const int m = mi * 8 + r;
        #pragma unroll
        for (int c = 0; c < 2; c++) {
            g_pR[kc][m * HH + n0 + ni*2 + c] = accR[r][c];
            g_pI[kc][m * HH + n0 + ni*2 + c] = accI[r][c];
        }
    }
}

// ---------------------------------------------------------------------------
// Pinned prefetch: asm volatile load cannot be sunk past the barrier by ptxas
// ---------------------------------------------------------------------------
__device__ __forceinline__ float4 ldg_v4_pinned(const float4* p) {
    float4 v;
    asm volatile("ld.global.nc.v4.f32 {%0,%1,%2,%3}, [%4];"
                 : "=f"(v.x), "=f"(v.y), "=f"(v.z), "=f"(v.w) : "l"(p));
    return v;
}

// ---------------------------------------------------------------------------
// Kernel 2: Clements mesh — ONE barrier + ONE smem round-trip per layer pair
//           (duplicated-MZI scheme, parity double-buffered exchange)
// ---------------------------------------------------------------------------
__global__ __launch_bounds__(512, 1) void k2(
    const float* __restrict__ stR, const float* __restrict__ stI,
    const float* __restrict__ bR,  const float* __restrict__ bI,
    const float* __restrict__ om,  const float* __restrict__ mb,
    float* __restrict__ out)
{
    const int b = blockIdx.x, t = threadIdx.x;
    __shared__ float4 exU[2][512];   // {s1*pr, s1*pi, c1, _} published by thread t
    __shared__ float2 exA[2][512];   // post-A (ar, ai) = channel 2t

    // thread t owns channels (2t, 2t+1)
    float2 vr = ((const float2*)(stR + b * HH))[t];
    float2 vi = ((const float2*)(stI + b * HH))[t];
    float ar = vr.x, br = vr.y, ai = vi.x, bi = vi.y;

    const int tp = (t < 511) ? t + 1 : t;   // clamped neighbor indices
    const int tm = (t > 0)   ? t - 1 : t;

    float4 ta = g_trigA[0][t];
    float4 tb = g_trigB[0][t];

    for (int k = 0; k < LP; k++) {
        // pinned prefetch of next layer pair's trig (used next iteration)
        const int kn = (k + 1 < LP) ? k + 1 : k;
        float4 taN = ldg_v4_pinned(&g_trigA[kn][t]);
        float4 tbN = ldg_v4_pinned(&g_trigB[kn][t]);

        // ---- layer A: pair (2t, 2t+1), thread-local ----
        float pr  = ta.x*ar - ta.y*ai;
        float pii = ta.y*ar + ta.x*ai;
        float nar = ta.z*pr  - ta.w*bi;
        float nai = ta.z*pii + ta.w*br;
        float nbr = ta.z*br  - ta.w*pii;
        float nbi = ta.z*bi  + ta.w*pr;
        ar = nar; ai = nai; br = nbr; bi = nbi;

        // ---- layer B publish: phase-shift own a-arm (channel 2t+1) ----
        float bpr = tb.x*br - tb.y*bi;
        float bpi = tb.y*br + tb.x*bi;
        const int buf = k & 1;
        exU[buf][t] = make_float4(tb.w*bpr, tb.w*bpi, tb.z, 0.f);
        exA[buf][t] = make_float2(ar, ai);

        __syncthreads();   // the ONLY barrier this iteration

        // a' of MZI(2t+1, 2t+2): new channel 2t+1 (mine)
        float2 na = exA[buf][tp];
        float obr = tb.z*bpr - tb.w*na.y;
        float obi = tb.z*bpi + tb.w*na.x;
        // b' of MZI(2t-1, 2t): new channel 2t (mine), via neighbor's published u
        float4 u  = exU[buf][tm];
        float oar = u.z*ar - u.y;
        float oai = u.z*ai + u.x;

        br = (t < 511) ? obr : br;
        bi = (t < 511) ? obi : bi;
        ar = (t > 0)   ? oar : ar;
        ai = (t > 0)   ? oai : ai;

        ta = taN; tb = tbN;
    }

    // ---- epilogue ----
    const int ch = 2 * t;
    float ihR0 = bR[ch],     ihI0 = bI[ch];
    float ihR1 = bR[ch + 1], ihI1 = bI[ch + 1];
    #pragma unroll
    for (int c = 0; c < 4; c++) {
        float2 pr2 = ((const float2*)&g_pR[c][b * HH])[t];
        float2 pi2 = ((const float2*)&g_pI[c][b * HH])[t];
        ihR0 += pr2.x; ihR1 += pr2.y;
        ihI0 += pi2.x; ihI1 += pi2.y;
    }

    float co0, so0, co1, so1;
    sincosf(om[ch],     &so0, &co0);
    sincosf(om[ch + 1], &so1, &co1);

    float zr0 = ihR0 + co0*ar - so0*ai;
    float zi0 = ihI0 + so0*ar + co0*ai;
    float zr1 = ihR1 + co1*br - so1*bi;
    float zi1 = ihI1 + so1*br + co1*bi;

    float mag0 = sqrtf(zr0*zr0 + zi0*zi0);
    float mag1 = sqrtf(zr1*zr1 + zi1*zi1);
    float sc0 = fmaxf(mag0 + mb[ch],     0.f) / fmaxf(mag0, 1e-8f);
    float sc1 = fmaxf(mag1 + mb[ch + 1], 0.f) / fmaxf(mag1, 1e-8f);

    ((float2*)(out + b * HH))[t]           = make_float2(sc0*zr0, sc1*zr1);
    ((float2*)(out + BB * HH + b * HH))[t] = make_float2(sc0*zi0, sc1*zi1);
}

// ---------------------------------------------------------------------------
extern "C" void kernel_launch(void* const* d_in, const int* in_sizes, int n_in,
                              void* d_out, int out_size)
{
    const float* inR = (const float*)d_in[0];
    const float* inI = (const float*)d_in[1];
    const float* stR = (const float*)d_in[2];
    const float* stI = (const float*)d_in[3];
    const float* wR  = (const float*)d_in[4];
    const float* wI  = (const float*)d_in[5];
    const float* bR  = (const float*)d_in[6];
    const float* bI  = (const float*)d_in[7];
    const float* A0  = (const float*)d_in[8];
    const float* A1  = (const float*)d_in[9];
    const float* B0  = (const float*)d_in[10];
    const float* B1  = (const float*)d_in[11];
    const float* om  = (const float*)d_in[12];
    const float* mb  = (const float*)d_in[13];
    float* out = (float*)d_out;

    k1<<<256, 256>>>(inR, inI, wR, wI, A0, A1, B0, B1);
    k2<<<128, 512>>>(stR, stI, bR, bI, om, mb, out);
}